// round 4
// baseline (speedup 1.0000x reference)
#include <cuda_runtime.h>

// Problem constants (fixed by setup_inputs)
#define B_   4
#define H_   64
#define W_   96
#define CH_  1152      // K*K*128
#define C_   128
#define S_   6
#define IMW_ 1536.0f
#define IMH_ 1024.0f

// Block = 1 ROI, 256 threads = 8 warps; each lane owns 4 channels (float4).
// Setup compacts valid y/x descriptors (validity & weights are separable),
// then pre-bakes per-sample-pair descriptors (4 offsets + 4 weights) in SMEM.
// Main loop: 2x LDS.128 + 4x LDG.128 + 16 FFMA per sample.

__global__ __launch_bounds__(256, 6) void rroi_kernel(
    const float* __restrict__ fm,
    const float* __restrict__ rois,
    float* __restrict__ out,
    int nroi)
{
    const int n = blockIdx.x;
    if (n >= nroi) return;

    const int tid  = threadIdx.x;
    const int wz   = tid >> 5;
    const int lane = tid & 31;

    // raw (uncompacted) descriptor tables
    __shared__ float tyw0[18], tyw1[18], txw0[18], txw1[18];
    __shared__ int   tyr0[18], tyr1[18], txc0[18], txc1[18];
    __shared__ int   tyv[18], txv[18];
    // compacted lists
    __shared__ int   cYr0[18], cYr1[18], cYch[18];
    __shared__ float cYw0[18], cYw1[18];
    __shared__ int   cXc0[18], cXc1[18], cXch[18];
    __shared__ float cXw0[18], cXw1[18];
    __shared__ int   sNy, sNx;
    // per-pair descriptors
    __shared__ int4   sOff[324];
    __shared__ float4 sWt[324];
    __shared__ float  part[8 * C_];

    // ROI params (broadcast loads)
    const float rb  = rois[n * 5 + 0];
    const float rx1 = rois[n * 5 + 1];
    const float ry1 = rois[n * 5 + 2];
    const float rx2 = rois[n * 5 + 3];
    const float ry2 = rois[n * 5 + 4];

    const int   b   = (int)rb;
    const float bx1 = rx1 / IMW_;
    const float by1 = ry1 / IMH_;
    const float bx2 = rx2 / IMW_;
    const float by2 = ry2 / IMH_;

    const float bin_w = (bx2 - bx1) / 3.0f;
    const float bin_h = by2 - by1 / 3.0f;      // reference bug, replicated

    // Phase 1: 18 y-descriptors (threads 0-17), 18 x-descriptors (threads 64-81)
    if (tid < 18) {
        const int d  = tid;
        const int ih = d / 6;
        const int sy = d - ih * 6;
        const float cy1 = by1 + (float)ih * bin_h;
        const float cy2 = by1 + (float)(ih + 1) * bin_h;
        const float ysv = cy1 * (float)(H_ - 1)
                        + (float)sy * ((cy2 - cy1) * (float)(H_ - 1) / (float)(S_ - 1));
        const int valid = (ysv >= 0.0f) && (ysv <= (float)(H_ - 1));
        const float y0f = floorf(ysv);
        const float ly  = ysv - y0f;
        int i0 = (int)y0f;
        i0 = i0 < 0 ? 0 : (i0 > H_ - 1 ? H_ - 1 : i0);
        int i1 = i0 + 1 > H_ - 1 ? H_ - 1 : i0 + 1;
        tyv[d]  = valid;
        tyr0[d] = i0 * (W_ * CH_);
        tyr1[d] = i1 * (W_ * CH_);
        tyw0[d] = 1.0f - ly;
        tyw1[d] = ly;
    } else if (tid >= 64 && tid < 82) {
        const int d  = tid - 64;
        const int iw = d / 6;
        const int sx = d - iw * 6;
        const float cx1 = bx1 + (float)iw * bin_w;
        const float cx2 = bx1 + (float)(iw + 1) * bin_h;   // reference bug, replicated
        const float xsv = cx1 * (float)(W_ - 1)
                        + (float)sx * ((cx2 - cx1) * (float)(W_ - 1) / (float)(S_ - 1));
        const int valid = (xsv >= 0.0f) && (xsv <= (float)(W_ - 1));
        const float x0f = floorf(xsv);
        const float lx  = xsv - x0f;
        int i0 = (int)x0f;
        i0 = i0 < 0 ? 0 : (i0 > W_ - 1 ? W_ - 1 : i0);
        int i1 = i0 + 1 > W_ - 1 ? W_ - 1 : i0 + 1;
        txv[d]  = valid;
        txc0[d] = i0 * CH_;
        txc1[d] = i1 * CH_;
        txw0[d] = 1.0f - lx;
        txw1[d] = lx;
    }
    __syncthreads();

    // Phase 2: compact valid descriptors (two threads in different warps)
    if (tid == 0) {
        int c = 0;
        #pragma unroll
        for (int d = 0; d < 18; ++d) {
            if (tyv[d]) {
                cYr0[c] = tyr0[d];
                cYr1[c] = tyr1[d];
                cYw0[c] = tyw0[d];
                cYw1[c] = tyw1[d];
                cYch[c] = (d / 6) * (3 * C_);   // ih*3*C
                ++c;
            }
        }
        sNy = c;
    } else if (tid == 32) {
        int c = 0;
        #pragma unroll
        for (int d = 0; d < 18; ++d) {
            if (txv[d]) {
                cXc0[c] = txc0[d];
                cXc1[c] = txc1[d];
                cXw0[c] = txw0[d];
                cXw1[c] = txw1[d];
                cXch[c] = (d / 6) * C_;         // iw*C
                ++c;
            }
        }
        sNx = c;
    }
    __syncthreads();

    const int ny = sNy, nx = sNx;
    const int total = ny * nx;

    // Phase 3: build per-pair descriptors
    for (int p = tid; p < total; p += 256) {
        const int yi = p / nx;
        const int xi = p - yi * nx;
        const int chb = cYch[yi] + cXch[xi];
        const int r0 = cYr0[yi], r1 = cYr1[yi];
        const int cA = cXc0[xi], cB = cXc1[xi];
        int4 o;
        o.x = r0 + cA + chb;
        o.y = r0 + cB + chb;
        o.z = r1 + cA + chb;
        o.w = r1 + cB + chb;
        sOff[p] = o;
        const float wy0 = cYw0[yi], wy1 = cYw1[yi];
        const float wx0 = cXw0[xi], wx1 = cXw1[xi];
        sWt[p] = make_float4(wy0 * wx0, wy0 * wx1, wy1 * wx0, wy1 * wx1);
    }
    __syncthreads();

    // Main loop: 8 warps stride the valid pairs; each lane holds 4 channels.
    const float* pb = fm + (size_t)b * (H_ * W_ * CH_) + lane * 4;

    float4 acc = make_float4(0.0f, 0.0f, 0.0f, 0.0f);

    for (int p = wz; p < total; p += 8) {
        const int4   o = sOff[p];
        const float4 w = sWt[p];

        const float4 f00 = *(const float4*)(pb + o.x);
        const float4 f01 = *(const float4*)(pb + o.y);
        const float4 f10 = *(const float4*)(pb + o.z);
        const float4 f11 = *(const float4*)(pb + o.w);

        acc.x += w.x * f00.x + w.y * f01.x + w.z * f10.x + w.w * f11.x;
        acc.y += w.x * f00.y + w.y * f01.y + w.z * f10.y + w.w * f11.y;
        acc.z += w.x * f00.z + w.y * f01.z + w.z * f10.z + w.w * f11.z;
        acc.w += w.x * f00.w + w.y * f01.w + w.z * f10.w + w.w * f11.w;
    }

    // Deterministic cross-warp reduction
    ((float4*)part)[wz * 32 + lane] = acc;
    __syncthreads();

    if (tid < C_) {
        float ssum = 0.0f;
        #pragma unroll
        for (int w = 0; w < 8; ++w) ssum += part[w * C_ + tid];
        out[n * C_ + tid] = ssum * (1.0f / 324.0f);
    }
}

extern "C" void kernel_launch(void* const* d_in, const int* in_sizes, int n_in,
                              void* d_out, int out_size) {
    const float* fm   = (const float*)d_in[0];
    const float* rois = (const float*)d_in[1];
    float* out        = (float*)d_out;
    const int nroi    = in_sizes[1] / 5;

    rroi_kernel<<<nroi, 256>>>(fm, rois, out, nroi);
}

// round 5
// speedup vs baseline: 1.1172x; 1.1172x over previous
#include <cuda_runtime.h>

// Problem constants (fixed by setup_inputs)
#define B_   4
#define H_   64
#define W_   96
#define CH_  1152      // K*K*128
#define C_   128
#define S_   6
#define IMW_ 1536.0f
#define IMH_ 1024.0f

// Block = 1 ROI, 256 threads = 8 warps; each lane owns 4 channels (float4).
// Setup compacts valid y/x descriptors (validity & weights are separable),
// pre-bakes per-pair descriptors (4 offsets + 4 weights) in SMEM.
// Main loop unrolled x2: 4x LDS.128 + 8x LDG.128 in flight + 32 FFMA.

__global__ __launch_bounds__(256, 4) void rroi_kernel(
    const float* __restrict__ fm,
    const float* __restrict__ rois,
    float* __restrict__ out,
    int nroi)
{
    const int n = blockIdx.x;
    if (n >= nroi) return;

    const int tid  = threadIdx.x;
    const int wz   = tid >> 5;
    const int lane = tid & 31;

    // raw (uncompacted) descriptor tables
    __shared__ float tyw0[18], tyw1[18], txw0[18], txw1[18];
    __shared__ int   tyr0[18], tyr1[18], txc0[18], txc1[18];
    __shared__ int   tyv[18], txv[18];
    // compacted lists
    __shared__ int   cYr0[18], cYr1[18], cYch[18];
    __shared__ float cYw0[18], cYw1[18];
    __shared__ int   cXc0[18], cXc1[18], cXch[18];
    __shared__ float cXw0[18], cXw1[18];
    __shared__ int   sNy, sNx;
    // per-pair descriptors
    __shared__ int4   sOff[324];
    __shared__ float4 sWt[324];
    __shared__ float  part[8 * C_];

    // ROI params (broadcast loads)
    const float rb  = rois[n * 5 + 0];
    const float rx1 = rois[n * 5 + 1];
    const float ry1 = rois[n * 5 + 2];
    const float rx2 = rois[n * 5 + 3];
    const float ry2 = rois[n * 5 + 4];

    const int   b   = (int)rb;
    const float bx1 = rx1 / IMW_;
    const float by1 = ry1 / IMH_;
    const float bx2 = rx2 / IMW_;
    const float by2 = ry2 / IMH_;

    const float bin_w = (bx2 - bx1) / 3.0f;
    const float bin_h = by2 - by1 / 3.0f;      // reference bug, replicated

    // Phase 1: 18 y-descriptors (threads 0-17), 18 x-descriptors (threads 64-81)
    if (tid < 18) {
        const int d  = tid;
        const int ih = d / 6;
        const int sy = d - ih * 6;
        const float cy1 = by1 + (float)ih * bin_h;
        const float cy2 = by1 + (float)(ih + 1) * bin_h;
        const float ysv = cy1 * (float)(H_ - 1)
                        + (float)sy * ((cy2 - cy1) * (float)(H_ - 1) / (float)(S_ - 1));
        const int valid = (ysv >= 0.0f) && (ysv <= (float)(H_ - 1));
        const float y0f = floorf(ysv);
        const float ly  = ysv - y0f;
        int i0 = (int)y0f;
        i0 = i0 < 0 ? 0 : (i0 > H_ - 1 ? H_ - 1 : i0);
        int i1 = i0 + 1 > H_ - 1 ? H_ - 1 : i0 + 1;
        tyv[d]  = valid;
        tyr0[d] = i0 * (W_ * CH_);
        tyr1[d] = i1 * (W_ * CH_);
        tyw0[d] = 1.0f - ly;
        tyw1[d] = ly;
    } else if (tid >= 64 && tid < 82) {
        const int d  = tid - 64;
        const int iw = d / 6;
        const int sx = d - iw * 6;
        const float cx1 = bx1 + (float)iw * bin_w;
        const float cx2 = bx1 + (float)(iw + 1) * bin_h;   // reference bug, replicated
        const float xsv = cx1 * (float)(W_ - 1)
                        + (float)sx * ((cx2 - cx1) * (float)(W_ - 1) / (float)(S_ - 1));
        const int valid = (xsv >= 0.0f) && (xsv <= (float)(W_ - 1));
        const float x0f = floorf(xsv);
        const float lx  = xsv - x0f;
        int i0 = (int)x0f;
        i0 = i0 < 0 ? 0 : (i0 > W_ - 1 ? W_ - 1 : i0);
        int i1 = i0 + 1 > W_ - 1 ? W_ - 1 : i0 + 1;
        txv[d]  = valid;
        txc0[d] = i0 * CH_;
        txc1[d] = i1 * CH_;
        txw0[d] = 1.0f - lx;
        txw1[d] = lx;
    }
    __syncthreads();

    // Phase 2: compact valid descriptors (two threads in different warps)
    if (tid == 0) {
        int c = 0;
        #pragma unroll
        for (int d = 0; d < 18; ++d) {
            if (tyv[d]) {
                cYr0[c] = tyr0[d];
                cYr1[c] = tyr1[d];
                cYw0[c] = tyw0[d];
                cYw1[c] = tyw1[d];
                cYch[c] = (d / 6) * (3 * C_);   // ih*3*C
                ++c;
            }
        }
        sNy = c;
    } else if (tid == 32) {
        int c = 0;
        #pragma unroll
        for (int d = 0; d < 18; ++d) {
            if (txv[d]) {
                cXc0[c] = txc0[d];
                cXc1[c] = txc1[d];
                cXw0[c] = txw0[d];
                cXw1[c] = txw1[d];
                cXch[c] = (d / 6) * C_;         // iw*C
                ++c;
            }
        }
        sNx = c;
    }
    __syncthreads();

    const int ny = sNy, nx = sNx;
    const int total = ny * nx;

    // Phase 3: build per-pair descriptors
    for (int p = tid; p < total; p += 256) {
        const int yi = p / nx;
        const int xi = p - yi * nx;
        const int chb = cYch[yi] + cXch[xi];
        const int r0 = cYr0[yi], r1 = cYr1[yi];
        const int cA = cXc0[xi], cB = cXc1[xi];
        int4 o;
        o.x = r0 + cA + chb;
        o.y = r0 + cB + chb;
        o.z = r1 + cA + chb;
        o.w = r1 + cB + chb;
        sOff[p] = o;
        const float wy0 = cYw0[yi], wy1 = cYw1[yi];
        const float wx0 = cXw0[xi], wx1 = cXw1[xi];
        sWt[p] = make_float4(wy0 * wx0, wy0 * wx1, wy1 * wx0, wy1 * wx1);
    }
    __syncthreads();

    // Main loop (unrolled x2): 8 warps stride the valid pairs.
    const float* pb = fm + (size_t)b * (H_ * W_ * CH_) + lane * 4;

    float4 acc0 = make_float4(0.0f, 0.0f, 0.0f, 0.0f);
    float4 acc1 = make_float4(0.0f, 0.0f, 0.0f, 0.0f);

    int p = wz;
    for (; p + 8 < total; p += 16) {
        const int4   oA = sOff[p];
        const int4   oB = sOff[p + 8];
        const float4 wA = sWt[p];
        const float4 wB = sWt[p + 8];

        // 8 independent LDG.128 in flight
        const float4 a00 = *(const float4*)(pb + oA.x);
        const float4 a01 = *(const float4*)(pb + oA.y);
        const float4 a10 = *(const float4*)(pb + oA.z);
        const float4 a11 = *(const float4*)(pb + oA.w);
        const float4 b00 = *(const float4*)(pb + oB.x);
        const float4 b01 = *(const float4*)(pb + oB.y);
        const float4 b10 = *(const float4*)(pb + oB.z);
        const float4 b11 = *(const float4*)(pb + oB.w);

        acc0.x += wA.x * a00.x + wA.y * a01.x + wA.z * a10.x + wA.w * a11.x;
        acc0.y += wA.x * a00.y + wA.y * a01.y + wA.z * a10.y + wA.w * a11.y;
        acc0.z += wA.x * a00.z + wA.y * a01.z + wA.z * a10.z + wA.w * a11.z;
        acc0.w += wA.x * a00.w + wA.y * a01.w + wA.z * a10.w + wA.w * a11.w;

        acc1.x += wB.x * b00.x + wB.y * b01.x + wB.z * b10.x + wB.w * b11.x;
        acc1.y += wB.x * b00.y + wB.y * b01.y + wB.z * b10.y + wB.w * b11.y;
        acc1.z += wB.x * b00.z + wB.y * b01.z + wB.z * b10.z + wB.w * b11.z;
        acc1.w += wB.x * b00.w + wB.y * b01.w + wB.z * b10.w + wB.w * b11.w;
    }
    if (p < total) {
        const int4   o = sOff[p];
        const float4 w = sWt[p];
        const float4 f00 = *(const float4*)(pb + o.x);
        const float4 f01 = *(const float4*)(pb + o.y);
        const float4 f10 = *(const float4*)(pb + o.z);
        const float4 f11 = *(const float4*)(pb + o.w);
        acc0.x += w.x * f00.x + w.y * f01.x + w.z * f10.x + w.w * f11.x;
        acc0.y += w.x * f00.y + w.y * f01.y + w.z * f10.y + w.w * f11.y;
        acc0.z += w.x * f00.z + w.y * f01.z + w.z * f10.z + w.w * f11.z;
        acc0.w += w.x * f00.w + w.y * f01.w + w.z * f10.w + w.w * f11.w;
    }

    acc0.x += acc1.x; acc0.y += acc1.y; acc0.z += acc1.z; acc0.w += acc1.w;

    // Deterministic cross-warp reduction
    ((float4*)part)[wz * 32 + lane] = acc0;
    __syncthreads();

    if (tid < C_) {
        float ssum = 0.0f;
        #pragma unroll
        for (int w = 0; w < 8; ++w) ssum += part[w * C_ + tid];
        out[n * C_ + tid] = ssum * (1.0f / 324.0f);
    }
}

extern "C" void kernel_launch(void* const* d_in, const int* in_sizes, int n_in,
                              void* d_out, int out_size) {
    const float* fm   = (const float*)d_in[0];
    const float* rois = (const float*)d_in[1];
    float* out        = (float*)d_out;
    const int nroi    = in_sizes[1] / 5;

    rroi_kernel<<<nroi, 256>>>(fm, rois, out, nroi);
}